// round 17
// baseline (speedup 1.0000x reference)
#include <cuda_runtime.h>

#define B_TOT 2048
#define H     51
#define HP    56           // padded rows 51..55 = zeros
#define KP    56           // padded k extent (floats), 14 u2
#define KU2   14
#define MSZ   (HP*KP)      // 3136 floats per gate matrix
#define E     16
#define TPB   448          // kh(2) x eg(4) x jr(56) = 14 warps
#define XCH   40

typedef unsigned long long ull;

struct __align__(16) Smem {
    float l1r[MSZ], l1z[MSZ], l1n[MSZ];
    float ir2[MSZ], iz2[MSZ], in2[MSZ];
    float hr2[MSZ], hz2[MSZ], hn2[MSZ];
    float wih1r[HP], wih1z[HP], wih1n[HP];
    float bR1[HP], bZ1[HP], bIN1[HP], bHN1[HP];
    float bR2[HP], bZ2[HP], bIN2[HP], bHN2[HP];
    float wlin[KP];
    float h1[2][E][KP];
    float h2[2][E][KP];
    float xbuf[E][XCH];
    float PO[4][4][16];    // [eg][ei][warp]; slots 14,15 stay 0
    float blin;
};

__device__ __forceinline__ void fma2(ull& d, ull a, ull b) {
    asm("fma.rn.f32x2 %0, %1, %2, %0;" : "+l"(d) : "l"(a), "l"(b));
}
__device__ __forceinline__ ull pack2(float a, float b) {
    ull r; asm("mov.b64 %0, {%1,%2};" : "=l"(r) : "f"(a), "f"(b)); return r;
}
__device__ __forceinline__ float sum2(ull v) {
    float a, b; asm("mov.b64 {%0,%1}, %2;" : "=f"(a), "=f"(b) : "l"(v));
    return a + b;
}
__device__ __forceinline__ float tanha_(float v) {
    float r; asm("tanh.approx.f32 %0, %1;" : "=f"(r) : "f"(v)); return r;
}
__device__ __forceinline__ float sigmoid_(float v) {
    return fmaf(0.5f, tanha_(0.5f * v), 0.5f);
}
__device__ __forceinline__ float gru_cell(float gr, float gz, float gin,
                                          float ghn, float ho) {
    float r = sigmoid_(gr);
    float z = sigmoid_(gz);
    float n = tanha_(fmaf(r, ghn, gin));
    return fmaf(z, ho - n, n);
}

// pair-exchange reduction over ei: lane kh keeps ei {2kh, 2kh+1}; 2 shfls
#define XR2(G0, G1, A)                                                    \
    {                                                                     \
        float _s0 = sum2(A[0]), _s1 = sum2(A[1]);                         \
        float _s2 = sum2(A[2]), _s3 = sum2(A[3]);                         \
        float _ka = kh ? _s2 : _s0, _kb = kh ? _s3 : _s1;                 \
        float _sa = kh ? _s0 : _s2, _sb = kh ? _s1 : _s3;                 \
        G0 = _ka + __shfl_xor_sync(0xFFFFFFFFu, _sa, 1);                  \
        G1 = _kb + __shfl_xor_sync(0xFFFFFFFFu, _sb, 1);                  \
    }

__device__ __forceinline__ void fill_mat(float* dst, const float* src, int g, int tid) {
    for (int idx = tid; idx < MSZ; idx += TPB) {
        int j = idx / KP, k = idx - j * KP;
        bool valid = (j < H) && (k < H);
        dst[idx] = valid ? src[(g * H + j) * H + k] : 0.f;
    }
}

__device__ __forceinline__ float outdot(Smem* s, const float* hrow) {
    const ulonglong2* hv = (const ulonglong2*)hrow;
    const ulonglong2* wl = (const ulonglong2*)s->wlin;
    ull acc = pack2(s->blin, 0.f);
    #pragma unroll
    for (int k = 0; k < KU2; k++) {
        ulonglong2 h = hv[k], w = wl[k];
        fma2(acc, h.x, w.x); fma2(acc, h.y, w.y);
    }
    return sum2(acc);
}

__device__ __forceinline__ float posum(Smem* s, int eg_, int ei_) {
    const float4* p = (const float4*)&s->PO[eg_][ei_][0];
    float4 a = p[0], b = p[1], c = p[2], d = p[3];
    return s->blin + a.x + a.y + a.z + a.w + b.x + b.y + b.z + b.w
                   + c.x + c.y + c.z + c.w + d.x + d.y + d.z + d.w;
}

// ---- layer 1: dot (half-k mainloop + pair-exchange) / fin ----
__device__ __forceinline__ void l1_dot(Smem* s, int rd,
                                       int jr, int kh, int kb, int eg,
                                       float gr[2], float gz[2], float gn[2])
{
    ull aR[4], aZ[4], aN[4];
    #pragma unroll
    for (int ei = 0; ei < 4; ei++) {
        aR[ei] = (kh == 0) ? pack2(s->bR1[jr], 0.f) : 0ull;
        aZ[ei] = (kh == 0) ? pack2(s->bZ1[jr], 0.f) : 0ull;
        aN[ei] = (kh == 0) ? pack2(s->bHN1[jr], 0.f) : 0ull;
    }
    const ulonglong2* pr = (const ulonglong2*)s->l1r + jr * KU2 + kb;
    const ulonglong2* pz = (const ulonglong2*)s->l1z + jr * KU2 + kb;
    const ulonglong2* pn = (const ulonglong2*)s->l1n + jr * KU2 + kb;
    const ulonglong2* ph = (const ulonglong2*)&s->h1[rd][0][0] + eg * KU2 + kb;
    #pragma unroll
    for (int ki = 0; ki < 7; ki++) {
        ulonglong2 wr = pr[ki], wz = pz[ki], wn = pn[ki];
        #pragma unroll
        for (int ei = 0; ei < 4; ei++) {
            ulonglong2 h = ph[ki + ei * 4 * KU2];
            fma2(aR[ei], h.x, wr.x); fma2(aR[ei], h.y, wr.y);
            fma2(aZ[ei], h.x, wz.x); fma2(aZ[ei], h.y, wz.y);
            fma2(aN[ei], h.x, wn.x); fma2(aN[ei], h.y, wn.y);
        }
    }
    XR2(gr[0], gr[1], aR);
    XR2(gz[0], gz[1], aZ);
    XR2(gn[0], gn[1], aN);
}

__device__ __forceinline__ void l1_fin(Smem* s, int rd, int wr, const float xv[2],
                                       const float gr[2], const float gz[2],
                                       const float gn[2], int jr, int e0)
{
    const float wr1 = s->wih1r[jr], wz1 = s->wih1z[jr];
    const float wn1 = s->wih1n[jr], bi  = s->bIN1[jr];
    #pragma unroll
    for (int q = 0; q < 2; q++) {
        int el = e0 + 4 * q;
        float ho = s->h1[rd][el][jr];
        float nh = gru_cell(fmaf(xv[q], wr1, gr[q]), fmaf(xv[q], wz1, gz[q]),
                            fmaf(xv[q], wn1, bi), gn[q], ho);
        s->h1[wr][el][jr] = nh;
    }
}

__device__ __forceinline__ void layer1(Smem* s, int rd, int wr, const float xv[2],
                                       int jr, int kh, int kb, int eg, int e0)
{
    float gr[2], gz[2], gn[2];
    l1_dot(s, rd, jr, kh, kb, eg, gr, gz, gn);
    l1_fin(s, rd, wr, xv, gr, gz, gn, jr, e0);
}

template<bool PO>
__device__ __forceinline__ void layer2(Smem* s, int ub, int vrd, int vwr,
                                       int jr, int kh, int kb, int eg, int e0,
                                       int lane, int warp)
{
    ull aR[4], aZ[4], aI[4], aH[4];
    #pragma unroll
    for (int ei = 0; ei < 4; ei++) {
        aR[ei] = (kh == 0) ? pack2(s->bR2[jr], 0.f) : 0ull;
        aZ[ei] = (kh == 0) ? pack2(s->bZ2[jr], 0.f) : 0ull;
        aI[ei] = (kh == 0) ? pack2(s->bIN2[jr], 0.f) : 0ull;
        aH[ei] = (kh == 0) ? pack2(s->bHN2[jr], 0.f) : 0ull;
    }
    const ulonglong2* pir = (const ulonglong2*)s->ir2 + jr * KU2 + kb;
    const ulonglong2* piz = (const ulonglong2*)s->iz2 + jr * KU2 + kb;
    const ulonglong2* pin = (const ulonglong2*)s->in2 + jr * KU2 + kb;
    const ulonglong2* phr = (const ulonglong2*)s->hr2 + jr * KU2 + kb;
    const ulonglong2* phz = (const ulonglong2*)s->hz2 + jr * KU2 + kb;
    const ulonglong2* phn = (const ulonglong2*)s->hn2 + jr * KU2 + kb;
    const ulonglong2* pu  = (const ulonglong2*)&s->h1[ub][0][0]  + eg * KU2 + kb;
    const ulonglong2* pv  = (const ulonglong2*)&s->h2[vrd][0][0] + eg * KU2 + kb;
    #pragma unroll
    for (int ki = 0; ki < 7; ki++) {
        ulonglong2 a = pir[ki], b = piz[ki], c = pin[ki];
        ulonglong2 d = phr[ki], e = phz[ki], f = phn[ki];
        #pragma unroll
        for (int ei = 0; ei < 4; ei++) {
            ulonglong2 u = pu[ki + ei * 4 * KU2];
            ulonglong2 v = pv[ki + ei * 4 * KU2];
            fma2(aR[ei], u.x, a.x); fma2(aR[ei], u.y, a.y);
            fma2(aR[ei], v.x, d.x); fma2(aR[ei], v.y, d.y);
            fma2(aZ[ei], u.x, b.x); fma2(aZ[ei], u.y, b.y);
            fma2(aZ[ei], v.x, e.x); fma2(aZ[ei], v.y, e.y);
            fma2(aI[ei], u.x, c.x); fma2(aI[ei], u.y, c.y);
            fma2(aH[ei], v.x, f.x); fma2(aH[ei], v.y, f.y);
        }
    }
    float gR[2], gZ[2], gI[2], gH[2];
    XR2(gR[0], gR[1], aR);
    XR2(gZ[0], gZ[1], aZ);
    XR2(gI[0], gI[1], aI);
    XR2(gH[0], gH[1], aH);
    float nh[2];
    #pragma unroll
    for (int q = 0; q < 2; q++) {
        int el = e0 + 4 * q;
        float ho = s->h2[vrd][el][jr];
        nh[q] = gru_cell(gR[q], gZ[q], gI[q], gH[q], ho);
        s->h2[vwr][el][jr] = nh[q];
    }
    if (PO) {
        float wlj = s->wlin[jr];    // rows 52..55: wlin = 0
        float p0 = nh[0] * wlj, p1 = nh[1] * wlj;
        p0 += __shfl_xor_sync(0xFFFFFFFFu, p0, 8);
        p0 += __shfl_xor_sync(0xFFFFFFFFu, p0, 16);
        p1 += __shfl_xor_sync(0xFFFFFFFFu, p1, 8);
        p1 += __shfl_xor_sync(0xFFFFFFFFu, p1, 16);
        if ((lane & 24) == 0) {
            s->PO[eg][2 * kh][warp]     = p0;
            s->PO[eg][2 * kh + 1][warp] = p1;
        }
    }
}

// ---- compile-time-parity step bodies ----
#define STAGE_X(i)                                                        \
    {                                                                     \
        for (int k_ = tid; k_ < E * XCH; k_ += TPB) {                     \
            int e_ = k_ / XCH, c_ = k_ - e_ * XCH;                        \
            int tg_ = (i) + c_;                                           \
            s->xbuf[e_][c_] = (tg_ < T) ? x[(size_t)(base + e_) * T + tg_] : 0.f; \
        }                                                                 \
        __syncthreads();                                                  \
    }

#define P1_STEP(i, PAR)                                                   \
    {                                                                     \
        const int xidx_ = (i) % XCH;                                      \
        if ((i) >= 2 && outw)                                             \
            myout[(i) - 2] = outdot(s, &s->h2[(PAR)][lane][0]);           \
        float xv_[2];                                                     \
        xv_[0] = s->xbuf[e0][xidx_];                                      \
        xv_[1] = s->xbuf[e0 + 4][xidx_];                                  \
        layer1(s, (PAR) ^ 1, (PAR), xv_, jr, kh, kb, eg, e0);             \
        if ((i) >= 1)                                                     \
            layer2<false>(s, (PAR) ^ 1, (PAR), (PAR) ^ 1,                 \
                          jr, kh, kb, eg, e0, lane, warp);                \
        __syncthreads();                                                  \
    }

#define BRIDGE(TP)                                                        \
    {                                                                     \
        if (outw) myout[T - 2] = outdot(s, &s->h2[(TP)][lane][0]);        \
        layer2<true>(s, (TP) ^ 1, (TP), (TP) ^ 1,                         \
                     jr, kh, kb, eg, e0, lane, warp);                     \
        l1_dot(s, (TP) ^ 1, jr, kh, kb, eg, g1r, g1z, g1n);               \
        __syncthreads();                                                  \
    }

#define P2_STEP(t, PAR)                                                   \
    {                                                                     \
        float xv_[2];                                                     \
        xv_[0] = posum(s, eg, 2 * kh);                                    \
        xv_[1] = posum(s, eg, 2 * kh + 1);                                \
        l1_fin(s, (PAR) ^ 1, (PAR), xv_, g1r, g1z, g1n, jr, e0);          \
        if (outw) myout[(t) - 1] = posum(s, lane & 3, lane >> 2);         \
        __syncthreads();                                                  \
        layer2<true>(s, (PAR), (PAR) ^ 1, (PAR),                          \
                     jr, kh, kb, eg, e0, lane, warp);                     \
        if ((t) + 1 < TF)                                                 \
            l1_dot(s, (PAR), jr, kh, kb, eg, g1r, g1z, g1n);              \
        __syncthreads();                                                  \
    }

__global__ void __launch_bounds__(TPB, 1) gru_stack_kernel(
    const float* __restrict__ x,
    const float* __restrict__ w_ih1, const float* __restrict__ w_hh1,
    const float* __restrict__ b_ih1, const float* __restrict__ b_hh1,
    const float* __restrict__ w_ih2, const float* __restrict__ w_hh2,
    const float* __restrict__ b_ih2, const float* __restrict__ b_hh2,
    const float* __restrict__ w_lin, const float* __restrict__ b_lin,
    float* __restrict__ out, int T, int F)
{
    extern __shared__ float smem_f[];
    Smem* s = reinterpret_cast<Smem*>(smem_f);

    const int tid  = threadIdx.x;
    const int kh   = tid & 1;
    const int eg   = (tid >> 1) & 3;
    const int jr   = tid >> 3;              // 0..55 (52..55 zero rows)
    const int kb   = kh * (KU2 / 2);
    const int e0   = eg + 8 * kh;           // finalized els e0, e0+4
    const int lane = tid & 31;
    const int warp = tid >> 5;              // 0..13
    const int base = blockIdx.x * E;
    const int TF   = T + F;
    const bool outw = (warp == 13) && (lane < 16);   // zero-row warp, 4-warp SMSP
    float* myout = out + (outw ? (size_t)(base + lane) * TF : 0);

    // ---------------- one-time init ----------------
    fill_mat(s->l1r, w_hh1, 0, tid); fill_mat(s->l1z, w_hh1, 1, tid); fill_mat(s->l1n, w_hh1, 2, tid);
    fill_mat(s->ir2, w_ih2, 0, tid); fill_mat(s->iz2, w_ih2, 1, tid); fill_mat(s->in2, w_ih2, 2, tid);
    fill_mat(s->hr2, w_hh2, 0, tid); fill_mat(s->hz2, w_hh2, 1, tid); fill_mat(s->hn2, w_hh2, 2, tid);
    for (int i = tid; i < HP; i += TPB) {
        bool v = (i < H);
        s->wih1r[i] = v ? w_ih1[i] : 0.f;
        s->wih1z[i] = v ? w_ih1[H + i] : 0.f;
        s->wih1n[i] = v ? w_ih1[2 * H + i] : 0.f;
        s->bR1[i]  = v ? (b_ih1[i] + b_hh1[i]) : 0.f;
        s->bZ1[i]  = v ? (b_ih1[H + i] + b_hh1[H + i]) : 0.f;
        s->bIN1[i] = v ? b_ih1[2 * H + i] : 0.f;
        s->bHN1[i] = v ? b_hh1[2 * H + i] : 0.f;
        s->bR2[i]  = v ? (b_ih2[i] + b_hh2[i]) : 0.f;
        s->bZ2[i]  = v ? (b_ih2[H + i] + b_hh2[H + i]) : 0.f;
        s->bIN2[i] = v ? b_ih2[2 * H + i] : 0.f;
        s->bHN2[i] = v ? b_hh2[2 * H + i] : 0.f;
    }
    for (int i = tid; i < KP; i += TPB) s->wlin[i] = (i < H) ? w_lin[i] : 0.f;
    if (tid == 0) s->blin = b_lin[0];
    {
        float* h1f = &s->h1[0][0][0];
        float* h2f = &s->h2[0][0][0];
        for (int i = tid; i < 2 * E * KP; i += TPB) { h1f[i] = 0.f; h2f[i] = 0.f; }
        float* pof = &s->PO[0][0][0];
        for (int i = tid; i < 4 * 4 * 16; i += TPB) pof[i] = 0.f;
    }
    __syncthreads();

    float g1r[2], g1z[2], g1n[2];

    // ================= phase 1 (teacher forced) =================
    int i = 0;
    for (; i + 1 < T; i += 2) {
        if ((i % XCH) == 0) STAGE_X(i);
        P1_STEP(i, 0);
        P1_STEP(i + 1, 1);
    }
    if (i < T) {
        if ((i % XCH) == 0) STAGE_X(i);
        P1_STEP(i, 0);
        i++;
    }

    // bridge
    if ((T & 1) == 0) BRIDGE(0) else BRIDGE(1);

    // ================= phase 2 (autoregressive) =================
    int t = T;
    if (t < TF && (t & 1)) { P2_STEP(t, 1); t++; }
    for (; t + 1 < TF; t += 2) {
        P2_STEP(t, 0);
        P2_STEP(t + 1, 1);
    }
    if (t < TF) { P2_STEP(t, 0); t++; }

    // final output (step TF-1)
    if (outw) myout[TF - 1] = posum(s, lane & 3, lane >> 2);
}

extern "C" void kernel_launch(void* const* d_in, const int* in_sizes, int n_in,
                              void* d_out, int out_size)
{
    const float* x     = (const float*)d_in[0];
    const float* w_ih1 = (const float*)d_in[1];
    const float* w_hh1 = (const float*)d_in[2];
    const float* b_ih1 = (const float*)d_in[3];
    const float* b_hh1 = (const float*)d_in[4];
    const float* w_ih2 = (const float*)d_in[5];
    const float* w_hh2 = (const float*)d_in[6];
    const float* b_ih2 = (const float*)d_in[7];
    const float* b_hh2 = (const float*)d_in[8];
    const float* w_lin = (const float*)d_in[9];
    const float* b_lin = (const float*)d_in[10];

    const int B  = B_TOT;
    const int T  = in_sizes[0] / B;
    const int TF = out_size / B;
    const int F  = TF - T;

    size_t shmem = sizeof(Smem);
    cudaFuncSetAttribute(gru_stack_kernel,
                         cudaFuncAttributeMaxDynamicSharedMemorySize, (int)shmem);

    gru_stack_kernel<<<B / E, TPB, shmem>>>(
        x, w_ih1, w_hh1, b_ih1, b_hh1,
        w_ih2, w_hh2, b_ih2, b_hh2,
        w_lin, b_lin, (float*)d_out, T, F);
}